// round 1
// baseline (speedup 1.0000x reference)
#include <cuda_runtime.h>

// Problem constants (match reference setup_inputs)
#define NTOK   8192      // 4 * 2048
#define DMODEL 512
#define NEXP   64
#define HEXP   256
#define HSH    512       // H * NSH
#define CAP    1024
#define RSCALE 2.5f

// ---------------- scratch (device globals; no allocations allowed) -------------
__device__ int   g_cnt[NEXP];
__device__ int   g_tok[NEXP * CAP];
__device__ float g_wgt[NEXP * CAP];
__device__ float g_h [(size_t)NEXP * CAP * HEXP];   // routed hidden, 67 MB
__device__ float g_hs[(size_t)NTOK * HSH];          // shared-expert hidden, 16 MB

// ---------------- k0: zero per-expert counters --------------------------------
__global__ void k_zero() {
    if (threadIdx.x < NEXP) g_cnt[threadIdx.x] = 0;
}

// ---------------- k1: router + dispatch ----------------------------------------
// 16 tokens per block, 128 threads. Each thread owns one expert row (e = tid&63)
// and computes logits for 8 of the 16 tokens. Then threads 0..15 do the top-2
// scan for one token each and atomically claim dispatch slots.
#define RTB 16
__global__ void k_router(const float* __restrict__ x, const float* __restrict__ gw) {
    __shared__ __align__(16) float xs[RTB][DMODEL];   // 32 KB
    __shared__ float sc[RTB][NEXP];                   // 4 KB
    const int tid = threadIdx.x;
    const int t0  = blockIdx.x * RTB;

    // cooperative load of 16 token rows
    const float4* src = (const float4*)(x + (size_t)t0 * DMODEL);
    float4* dst = (float4*)&xs[0][0];
    #pragma unroll
    for (int i = tid; i < RTB * DMODEL / 4; i += 128) dst[i] = src[i];
    __syncthreads();

    const int e    = tid & 63;
    const int half = tid >> 6;              // 0 or 1 -> token subset
    const float* g = gw + (size_t)e * DMODEL;

    float acc[8];
    #pragma unroll
    for (int j = 0; j < 8; ++j) acc[j] = 0.f;

    for (int d = 0; d < DMODEL; d += 4) {
        const float4 gv = *(const float4*)(g + d);
        #pragma unroll
        for (int j = 0; j < 8; ++j) {
            const int tt = half * 8 + j;
            acc[j] = fmaf(gv.x, xs[tt][d],     acc[j]);
            acc[j] = fmaf(gv.y, xs[tt][d + 1], acc[j]);
            acc[j] = fmaf(gv.z, xs[tt][d + 2], acc[j]);
            acc[j] = fmaf(gv.w, xs[tt][d + 3], acc[j]);
        }
    }
    #pragma unroll
    for (int j = 0; j < 8; ++j)
        sc[half * 8 + j][e] = 1.f / (1.f + __expf(-acc[j]));
    __syncthreads();

    if (tid < RTB) {
        const int t = t0 + tid;
        float s0 = -1.f, s1 = -1.f; int e0 = 0, e1 = 0;
        #pragma unroll 8
        for (int i = 0; i < NEXP; ++i) {
            const float s = sc[tid][i];
            if (s > s0)      { s1 = s0; e1 = e0; s0 = s; e0 = i; }
            else if (s > s1) { s1 = s;  e1 = i; }
        }
        const float inv = RSCALE / (s0 + s1 + 1e-20f);
        const float w0 = s0 * inv, w1 = s1 * inv;
        int p0 = atomicAdd(&g_cnt[e0], 1);
        if (p0 < CAP) { g_tok[e0 * CAP + p0] = t; g_wgt[e0 * CAP + p0] = w0; }
        int p1 = atomicAdd(&g_cnt[e1], 1);
        if (p1 < CAP) { g_tok[e1 * CAP + p1] = t; g_wgt[e1 * CAP + p1] = w1; }
    }
}

// ---------------- shared expert FFN1: g_hs = silu(X@sw1) * (X@sw3) -------------
// 64x64 tile, BK=16, 256 threads, 4x4 microtile, two B operands.
__global__ void k_sffn1(const float* __restrict__ X,
                        const float* __restrict__ B1g,
                        const float* __restrict__ B3g) {
    __shared__ __align__(16) float As [16][64];
    __shared__ __align__(16) float Bs1[16][64];
    __shared__ __align__(16) float Bs3[16][64];
    const int tid = threadIdx.x;
    const int tx = tid & 15, ty = tid >> 4;
    const int m0 = blockIdx.x * 64, n0 = blockIdx.y * 64;
    const int ar = tid >> 2, ac = (tid & 3) << 2;
    const int br = tid >> 4, bc = (tid & 15) << 2;

    float acc1[4][4], acc3[4][4];
    #pragma unroll
    for (int i = 0; i < 4; ++i)
        #pragma unroll
        for (int j = 0; j < 4; ++j) { acc1[i][j] = 0.f; acc3[i][j] = 0.f; }

    for (int k0 = 0; k0 < DMODEL; k0 += 16) {
        const float4 av = *(const float4*)(X + (size_t)(m0 + ar) * DMODEL + k0 + ac);
        As[ac][ar] = av.x; As[ac + 1][ar] = av.y; As[ac + 2][ar] = av.z; As[ac + 3][ar] = av.w;
        *(float4*)&Bs1[br][bc] = *(const float4*)(B1g + (size_t)(k0 + br) * HSH + n0 + bc);
        *(float4*)&Bs3[br][bc] = *(const float4*)(B3g + (size_t)(k0 + br) * HSH + n0 + bc);
        __syncthreads();
        #pragma unroll
        for (int k = 0; k < 16; ++k) {
            const float4 a4 = *(const float4*)&As [k][ty * 4];
            const float4 p4 = *(const float4*)&Bs1[k][tx * 4];
            const float4 q4 = *(const float4*)&Bs3[k][tx * 4];
            const float aa[4] = {a4.x, a4.y, a4.z, a4.w};
            const float pp[4] = {p4.x, p4.y, p4.z, p4.w};
            const float qq[4] = {q4.x, q4.y, q4.z, q4.w};
            #pragma unroll
            for (int i = 0; i < 4; ++i)
                #pragma unroll
                for (int j = 0; j < 4; ++j) {
                    acc1[i][j] = fmaf(aa[i], pp[j], acc1[i][j]);
                    acc3[i][j] = fmaf(aa[i], qq[j], acc3[i][j]);
                }
        }
        __syncthreads();
    }
    #pragma unroll
    for (int i = 0; i < 4; ++i) {
        float4 o;
        float v[4];
        #pragma unroll
        for (int j = 0; j < 4; ++j) {
            const float z = acc1[i][j];
            v[j] = (z / (1.f + __expf(-z))) * acc3[i][j];
        }
        o.x = v[0]; o.y = v[1]; o.z = v[2]; o.w = v[3];
        *(float4*)&g_hs[(size_t)(m0 + ty * 4 + i) * HSH + n0 + tx * 4] = o;
    }
}

// ---------------- shared expert FFN2: out = g_hs @ sw2 -------------------------
__global__ void k_sffn2(const float* __restrict__ B2g, float* __restrict__ out) {
    __shared__ __align__(16) float As[16][64];
    __shared__ __align__(16) float Bs[16][64];
    const int tid = threadIdx.x;
    const int tx = tid & 15, ty = tid >> 4;
    const int m0 = blockIdx.x * 64, n0 = blockIdx.y * 64;
    const int ar = tid >> 2, ac = (tid & 3) << 2;
    const int br = tid >> 4, bc = (tid & 15) << 2;

    float acc[4][4];
    #pragma unroll
    for (int i = 0; i < 4; ++i)
        #pragma unroll
        for (int j = 0; j < 4; ++j) acc[i][j] = 0.f;

    for (int k0 = 0; k0 < HSH; k0 += 16) {
        const float4 av = *(const float4*)(&g_hs[(size_t)(m0 + ar) * HSH + k0 + ac]);
        As[ac][ar] = av.x; As[ac + 1][ar] = av.y; As[ac + 2][ar] = av.z; As[ac + 3][ar] = av.w;
        *(float4*)&Bs[br][bc] = *(const float4*)(B2g + (size_t)(k0 + br) * DMODEL + n0 + bc);
        __syncthreads();
        #pragma unroll
        for (int k = 0; k < 16; ++k) {
            const float4 a4 = *(const float4*)&As[k][ty * 4];
            const float4 b4 = *(const float4*)&Bs[k][tx * 4];
            const float aa[4] = {a4.x, a4.y, a4.z, a4.w};
            const float bb[4] = {b4.x, b4.y, b4.z, b4.w};
            #pragma unroll
            for (int i = 0; i < 4; ++i)
                #pragma unroll
                for (int j = 0; j < 4; ++j)
                    acc[i][j] = fmaf(aa[i], bb[j], acc[i][j]);
        }
        __syncthreads();
    }
    #pragma unroll
    for (int i = 0; i < 4; ++i) {
        float4 o; o.x = acc[i][0]; o.y = acc[i][1]; o.z = acc[i][2]; o.w = acc[i][3];
        *(float4*)&out[(size_t)(m0 + ty * 4 + i) * DMODEL + n0 + tx * 4] = o;
    }
}

// ---------------- routed FFN1: g_h = silu(Xg@w1[e]) * (Xg@w3[e]) ----------------
// grid (CAP/64, HEXP/64, NEXP); rows gathered via g_tok.
__global__ void k_effn1(const float* __restrict__ X,
                        const float* __restrict__ W1,
                        const float* __restrict__ W3) {
    const int e = blockIdx.z;
    const int cnt = min(g_cnt[e], CAP);
    const int m0 = blockIdx.x * 64;
    if (m0 >= cnt) return;
    const int n0 = blockIdx.y * 64;

    __shared__ __align__(16) float As [16][64];
    __shared__ __align__(16) float Bs1[16][64];
    __shared__ __align__(16) float Bs3[16][64];
    const int tid = threadIdx.x;
    const int tx = tid & 15, ty = tid >> 4;
    const int ar = tid >> 2, ac = (tid & 3) << 2;
    const int br = tid >> 4, bc = (tid & 15) << 2;

    const int myrow = m0 + ar;
    const int tok = (myrow < cnt) ? g_tok[e * CAP + myrow] : -1;
    const float* B1g = W1 + (size_t)e * DMODEL * HEXP;
    const float* B3g = W3 + (size_t)e * DMODEL * HEXP;

    float acc1[4][4], acc3[4][4];
    #pragma unroll
    for (int i = 0; i < 4; ++i)
        #pragma unroll
        for (int j = 0; j < 4; ++j) { acc1[i][j] = 0.f; acc3[i][j] = 0.f; }

    for (int k0 = 0; k0 < DMODEL; k0 += 16) {
        float4 av = make_float4(0.f, 0.f, 0.f, 0.f);
        if (tok >= 0) av = *(const float4*)(X + (size_t)tok * DMODEL + k0 + ac);
        As[ac][ar] = av.x; As[ac + 1][ar] = av.y; As[ac + 2][ar] = av.z; As[ac + 3][ar] = av.w;
        *(float4*)&Bs1[br][bc] = *(const float4*)(B1g + (size_t)(k0 + br) * HEXP + n0 + bc);
        *(float4*)&Bs3[br][bc] = *(const float4*)(B3g + (size_t)(k0 + br) * HEXP + n0 + bc);
        __syncthreads();
        #pragma unroll
        for (int k = 0; k < 16; ++k) {
            const float4 a4 = *(const float4*)&As [k][ty * 4];
            const float4 p4 = *(const float4*)&Bs1[k][tx * 4];
            const float4 q4 = *(const float4*)&Bs3[k][tx * 4];
            const float aa[4] = {a4.x, a4.y, a4.z, a4.w};
            const float pp[4] = {p4.x, p4.y, p4.z, p4.w};
            const float qq[4] = {q4.x, q4.y, q4.z, q4.w};
            #pragma unroll
            for (int i = 0; i < 4; ++i)
                #pragma unroll
                for (int j = 0; j < 4; ++j) {
                    acc1[i][j] = fmaf(aa[i], pp[j], acc1[i][j]);
                    acc3[i][j] = fmaf(aa[i], qq[j], acc3[i][j]);
                }
        }
        __syncthreads();
    }
    #pragma unroll
    for (int i = 0; i < 4; ++i) {
        const int r = m0 + ty * 4 + i;
        if (r < cnt) {
            float4 o;
            float v[4];
            #pragma unroll
            for (int j = 0; j < 4; ++j) {
                const float z = acc1[i][j];
                v[j] = (z / (1.f + __expf(-z))) * acc3[i][j];
            }
            o.x = v[0]; o.y = v[1]; o.z = v[2]; o.w = v[3];
            *(float4*)&g_h[((size_t)e * CAP + r) * HEXP + n0 + tx * 4] = o;
        }
    }
}

// ---------------- routed FFN2 + combine: out[t] += w * (g_h @ w2[e]) ------------
// grid (CAP/64, DMODEL/64, NEXP)
__global__ void k_effn2(const float* __restrict__ W2, float* __restrict__ out) {
    const int e = blockIdx.z;
    const int cnt = min(g_cnt[e], CAP);
    const int m0 = blockIdx.x * 64;
    if (m0 >= cnt) return;
    const int n0 = blockIdx.y * 64;

    __shared__ __align__(16) float As[16][64];
    __shared__ __align__(16) float Bs[16][64];
    const int tid = threadIdx.x;
    const int tx = tid & 15, ty = tid >> 4;
    const int ar = tid >> 2, ac = (tid & 3) << 2;
    const int br = tid >> 4, bc = (tid & 15) << 2;

    const int arow = m0 + ar;
    const bool avalid = (arow < cnt);
    const float* B2g = W2 + (size_t)e * HEXP * DMODEL;

    float acc[4][4];
    #pragma unroll
    for (int i = 0; i < 4; ++i)
        #pragma unroll
        for (int j = 0; j < 4; ++j) acc[i][j] = 0.f;

    for (int k0 = 0; k0 < HEXP; k0 += 16) {
        float4 av = make_float4(0.f, 0.f, 0.f, 0.f);
        if (avalid) av = *(const float4*)(&g_h[((size_t)e * CAP + arow) * HEXP + k0 + ac]);
        As[ac][ar] = av.x; As[ac + 1][ar] = av.y; As[ac + 2][ar] = av.z; As[ac + 3][ar] = av.w;
        *(float4*)&Bs[br][bc] = *(const float4*)(B2g + (size_t)(k0 + br) * DMODEL + n0 + bc);
        __syncthreads();
        #pragma unroll
        for (int k = 0; k < 16; ++k) {
            const float4 a4 = *(const float4*)&As[k][ty * 4];
            const float4 b4 = *(const float4*)&Bs[k][tx * 4];
            const float aa[4] = {a4.x, a4.y, a4.z, a4.w};
            const float bb[4] = {b4.x, b4.y, b4.z, b4.w};
            #pragma unroll
            for (int i = 0; i < 4; ++i)
                #pragma unroll
                for (int j = 0; j < 4; ++j)
                    acc[i][j] = fmaf(aa[i], bb[j], acc[i][j]);
        }
        __syncthreads();
    }
    #pragma unroll
    for (int i = 0; i < 4; ++i) {
        const int r = m0 + ty * 4 + i;
        if (r < cnt) {
            const int   t = g_tok[e * CAP + r];
            const float w = g_wgt[e * CAP + r];
            #pragma unroll
            for (int j = 0; j < 4; ++j)
                atomicAdd(&out[(size_t)t * DMODEL + n0 + tx * 4 + j], w * acc[i][j]);
        }
    }
}

// ---------------- launch ---------------------------------------------------------
extern "C" void kernel_launch(void* const* d_in, const int* in_sizes, int n_in,
                              void* d_out, int out_size) {
    const float* x    = (const float*)d_in[0];
    const float* gate = (const float*)d_in[1];
    const float* w1   = (const float*)d_in[2];
    const float* w3   = (const float*)d_in[3];
    const float* w2   = (const float*)d_in[4];
    const float* sw1  = (const float*)d_in[5];
    const float* sw3  = (const float*)d_in[6];
    const float* sw2  = (const float*)d_in[7];
    float* out = (float*)d_out;

    k_zero<<<1, 64>>>();
    k_router<<<NTOK / RTB, 128>>>(x, gate);
    k_sffn1<<<dim3(NTOK / 64, HSH / 64), 256>>>(x, sw1, sw3);
    k_sffn2<<<dim3(NTOK / 64, DMODEL / 64), 256>>>(sw2, out);
    k_effn1<<<dim3(CAP / 64, HEXP / 64, NEXP), 256>>>(x, w1, w3);
    k_effn2<<<dim3(CAP / 64, DMODEL / 64, NEXP), 256>>>(w2, out);
}